// round 15
// baseline (speedup 1.0000x reference)
#include <cuda_runtime.h>

#define B    32
#define E    512
#define HW   256
#define NH   8
#define HD   64
#define S    257
#define NCH  32    // e-chunks for logits
#define ECH  16    // 16 e per chunk

// ---------------- scratch (device globals; no allocation allowed) ----------------
__device__ float g_XPR[B * E * HW],   g_XPI[B * E * HW];    // x + pos, [b,e,hw]
__device__ float g_X0R[B * E],        g_X0I[B * E];         // mean token + pos, s=0
__device__ float g_QR [B * E],        g_QI [B * E];         // q projection at s=0
__device__ float g_QKR[B * NH * E],   g_QKI[B * NH * E];    // q folded into w_k (incl 1/8)
__device__ float g_LR [B * NH * S],   g_LI [B * NH * S];    // logits (atomic accum)
__device__ float g_L0R[B * NH],       g_L0I[B * NH];        // s=0 logit
__device__ float g_WR[B * NH * S],    g_WI[B * NH * S];     // softmax weights
__device__ float g_XWR[B * NH * E],   g_XWI[B * NH * E];    // sum_s w_s * x[s,e]
__device__ float g_ATR[B * E],        g_ATI[B * E];         // attention output row
__device__ float g_OR[B * E],         g_OI[B * E];          // after out-projection

// complex fused-multiply-add: (ar,ai) += (xr + i xi) * (yr + i yi)
__device__ __forceinline__ void cfma(float& ar, float& ai,
                                     float xr, float xi, float yr, float yi) {
    ar = fmaf(xr, yr, ar); ar = fmaf(-xi, yi, ar);
    ai = fmaf(xr, yi, ai); ai = fmaf(xi, yr, ai);
}

// warp-collective complex dot of one weight row (length E, float4 loads) with smem x
__device__ __forceinline__ void cdot_row(const float* __restrict__ wrow_r,
                                         const float* __restrict__ wrow_i,
                                         const float2* __restrict__ xc,
                                         int lane, float& ar, float& ai) {
    const float4* wr4 = (const float4*)wrow_r;
    const float4* wi4 = (const float4*)wrow_i;
    ar = 0.f; ai = 0.f;
    #pragma unroll
    for (int j = 0; j < E / 128; j++) {             // 4 iterations
        float4 a = wr4[j * 32 + lane];
        float4 c = wi4[j * 32 + lane];
        int e = (j * 32 + lane) * 4;
        float2 x0 = xc[e], x1 = xc[e + 1], x2 = xc[e + 2], x3 = xc[e + 3];
        cfma(ar, ai, x0.x, x0.y, a.x, c.x);
        cfma(ar, ai, x1.x, x1.y, a.y, c.y);
        cfma(ar, ai, x2.x, x2.y, a.z, c.z);
        cfma(ar, ai, x3.x, x3.y, a.w, c.w);
    }
    #pragma unroll
    for (int o = 16; o; o >>= 1) {
        ar += __shfl_xor_sync(0xffffffffu, ar, o);
        ai += __shfl_xor_sync(0xffffffffu, ai, o);
    }
}

// ---------------- 0. zero the logits accumulators ----------------
__global__ void k_zero() {
    int i = blockIdx.x * 256 + threadIdx.x;
    if (i < B * NH * S) { g_LR[i] = 0.f; g_LI[i] = 0.f; }
}

// ---------------- 1. mean + stage XP = x + pos ----------------
// one warp per (b,e) row; grid (B, 64) x 8 warps
__global__ void k_prep(const float* __restrict__ xr, const float* __restrict__ xi,
                       const float* __restrict__ pr, const float* __restrict__ pi) {
    int b = blockIdx.x;
    int warp = threadIdx.x >> 5, lane = threadIdx.x & 31;
    int e = blockIdx.y * 8 + warp;
    size_t rbase = ((size_t)b * E + e) * HW;
    const float4* rowr = (const float4*)(xr + rbase);
    const float4* rowi = (const float4*)(xi + rbase);
    float4* xpr4 = (float4*)(g_XPR + rbase);
    float4* xpi4 = (float4*)(g_XPI + rbase);
    const float* prow = pr + (size_t)e * S + 1;            // pos at s = hw+1
    const float* pirow = pi + (size_t)e * S + 1;
    float sr = 0.f, si = 0.f;
    #pragma unroll
    for (int half = 0; half < 2; half++) {
        int idx = lane + 32 * half;
        float4 a = rowr[idx], c = rowi[idx];
        sr += (a.x + a.y) + (a.z + a.w);
        si += (c.x + c.y) + (c.z + c.w);
        int hw = idx * 4;
        float4 o, p;
        o.x = a.x + prow[hw + 0]; o.y = a.y + prow[hw + 1];
        o.z = a.z + prow[hw + 2]; o.w = a.w + prow[hw + 3];
        p.x = c.x + pirow[hw + 0]; p.y = c.y + pirow[hw + 1];
        p.z = c.z + pirow[hw + 2]; p.w = c.w + pirow[hw + 3];
        xpr4[idx] = o; xpi4[idx] = p;
    }
    #pragma unroll
    for (int o = 16; o; o >>= 1) {
        sr += __shfl_xor_sync(0xffffffffu, sr, o);
        si += __shfl_xor_sync(0xffffffffu, si, o);
    }
    if (lane == 0) {
        g_X0R[b * E + e] = sr * (1.f / HW) + pr[(size_t)e * S + 0];
        g_X0I[b * E + e] = si * (1.f / HW) + pi[(size_t)e * S + 0];
    }
}

// ---------------- 2a. q[b,f] = sum_e x0[b,e] * w_in[f,e] + b_in[f] ----------------
__global__ void k_q(const float* __restrict__ wr, const float* __restrict__ wi,
                    const float* __restrict__ br, const float* __restrict__ bi) {
    int b = blockIdx.x, t = threadIdx.x, warp = t >> 5, lane = t & 31;  // 256 thr
    __shared__ float2 xc[E];
    for (int e = t; e < E; e += 256)
        xc[e] = make_float2(g_X0R[b * E + e], g_X0I[b * E + e]);
    __syncthreads();
    int f0 = blockIdx.y * 64;
    #pragma unroll
    for (int k = 0; k < 8; k++) {
        int f = f0 + warp + 8 * k;
        float ar, ai;
        cdot_row(wr + (size_t)f * E, wi + (size_t)f * E, xc, lane, ar, ai);
        if (lane == 0) {
            g_QR[b * E + f] = ar + br[f];
            g_QI[b * E + f] = ai + bi[f];
        }
    }
}

// ---------------- 2b. qk[b,h,e] = (1/8) sum_d q[b,h,d]*w_k[hd,e]; also s=0 logit ---
__global__ void k_qk(const float* __restrict__ wr, const float* __restrict__ wi) {
    int b = blockIdx.x, h = blockIdx.y, t = threadIdx.x;   // 512 threads, t = e
    int warp = t >> 5, lane = t & 31;
    __shared__ float2 qs[HD];
    __shared__ float sred[16][2];
    if (t < HD)
        qs[t] = make_float2(g_QR[b * E + h * HD + t] * 0.125f,
                            g_QI[b * E + h * HD + t] * 0.125f);
    __syncthreads();
    float ar = 0.f, ai = 0.f;
    #pragma unroll 8
    for (int d = 0; d < HD; d++) {
        size_t row = (size_t)(E + h * HD + d) * E + t;     // k block: rows [E, 2E)
        cfma(ar, ai, qs[d].x, qs[d].y, wr[row], wi[row]);
    }
    g_QKR[(b * NH + h) * E + t] = ar;
    g_QKI[(b * NH + h) * E + t] = ai;
    // s=0 logit: sum_e x0[b,e] * qk[b,h,e]
    float x0r = g_X0R[b * E + t], x0i = g_X0I[b * E + t];
    float p_r = 0.f, p_i = 0.f;
    cfma(p_r, p_i, x0r, x0i, ar, ai);
    #pragma unroll
    for (int o = 16; o; o >>= 1) {
        p_r += __shfl_xor_sync(0xffffffffu, p_r, o);
        p_i += __shfl_xor_sync(0xffffffffu, p_i, o);
    }
    if (lane == 0) { sred[warp][0] = p_r; sred[warp][1] = p_i; }
    __syncthreads();
    if (t == 0) {
        float a = 0.f, c = 0.f;
        #pragma unroll
        for (int w = 0; w < 16; w++) { a += sred[w][0]; c += sred[w][1]; }
        g_L0R[b * NH + h] = a;
        g_L0I[b * NH + h] = c;
    }
}

// ---------------- 3. logits: atomic-accumulate over e chunks ----------------
// grid (B, NCH), 128 threads; thread t handles s = 2t+1, 2t+2 via float2 XP loads
__global__ void k_logits() {
    int b = blockIdx.x, c = blockIdx.y, t = threadIdx.x;   // 128 threads
    __shared__ float2 qk[NH][ECH];
    int e0 = c * ECH;
    {
        int h = t / ECH, e = t % ECH;                      // 128 = NH*ECH exactly
        qk[h][e] = make_float2(g_QKR[(b * NH + h) * E + e0 + e],
                               g_QKI[(b * NH + h) * E + e0 + e]);
    }
    __syncthreads();
    int hw0 = 2 * t;
    float lr0[NH], li0[NH], lr1[NH], li1[NH];
    #pragma unroll
    for (int h = 0; h < NH; h++) { lr0[h] = li0[h] = lr1[h] = li1[h] = 0.f; }
    #pragma unroll 4
    for (int ee = 0; ee < ECH; ee++) {
        size_t base = ((size_t)b * E + e0 + ee) * HW + hw0;
        float2 xrv = *(const float2*)&g_XPR[base];
        float2 xiv = *(const float2*)&g_XPI[base];
        #pragma unroll
        for (int h = 0; h < NH; h++) {
            float2 q = qk[h][ee];
            cfma(lr0[h], li0[h], xrv.x, xiv.x, q.x, q.y);
            cfma(lr1[h], li1[h], xrv.y, xiv.y, q.x, q.y);
        }
    }
    int s = hw0 + 1;
    #pragma unroll
    for (int h = 0; h < NH; h++) {
        int base = (b * NH + h) * S + s;
        atomicAdd(&g_LR[base],     lr0[h]);
        atomicAdd(&g_LR[base + 1], lr1[h]);
        atomicAdd(&g_LI[base],     li0[h]);
        atomicAdd(&g_LI[base + 1], li1[h]);
    }
}

// ---------------- 4. softmax over s, separately on real and imag parts ----------
__global__ void k_softmax() {
    int b = blockIdx.x, h = blockIdx.y, t = threadIdx.x;   // 288 threads = 9 warps
    __shared__ float swr[9], swi[9], smax[2], ssum[2];
    bool act = t < S;
    float vr = 0.f, vi = 0.f;
    if (act) {
        if (t == 0) { vr = g_L0R[b * NH + h]; vi = g_L0I[b * NH + h]; }
        else        { vr = g_LR[(b * NH + h) * S + t]; vi = g_LI[(b * NH + h) * S + t]; }
    }
    int warp = t >> 5, lane = t & 31;
    float mr = act ? vr : -1e30f, mi = act ? vi : -1e30f;
    #pragma unroll
    for (int o = 16; o; o >>= 1) {
        mr = fmaxf(mr, __shfl_xor_sync(0xffffffffu, mr, o));
        mi = fmaxf(mi, __shfl_xor_sync(0xffffffffu, mi, o));
    }
    if (lane == 0) { swr[warp] = mr; swi[warp] = mi; }
    __syncthreads();
    if (t == 0) {
        float a = -1e30f, c2 = -1e30f;
        for (int w = 0; w < 9; w++) { a = fmaxf(a, swr[w]); c2 = fmaxf(c2, swi[w]); }
        smax[0] = a; smax[1] = c2;
    }
    __syncthreads();
    float er = act ? expf(vr - smax[0]) : 0.f;
    float ei = act ? expf(vi - smax[1]) : 0.f;
    float sr = er, si = ei;
    #pragma unroll
    for (int o = 16; o; o >>= 1) {
        sr += __shfl_xor_sync(0xffffffffu, sr, o);
        si += __shfl_xor_sync(0xffffffffu, si, o);
    }
    __syncthreads();
    if (lane == 0) { swr[warp] = sr; swi[warp] = si; }
    __syncthreads();
    if (t == 0) {
        float a = 0.f, c2 = 0.f;
        for (int w = 0; w < 9; w++) { a += swr[w]; c2 += swi[w]; }
        ssum[0] = a; ssum[1] = c2;
    }
    __syncthreads();
    if (act) {
        g_WR[(b * NH + h) * S + t] = er / ssum[0];
        g_WI[(b * NH + h) * S + t] = ei / ssum[1];
    }
}

// ---------------- 5. xw[b,h,e] = sum_s w[b,h,s] * xp[b,s,e] (complex) -------------
__global__ void k_xw() {
    int b = blockIdx.x;
    int t = threadIdx.x, warp = t >> 5, lane = t & 31;     // 512 thr = 16 warps
    int e = blockIdx.y * 16 + warp;
    __shared__ float2 ws[NH][S];                           // 16448 B
    for (int idx = t; idx < NH * S; idx += 512) {
        int h = idx / S, s = idx % S;
        ws[h][s] = make_float2(g_WR[(b * NH + h) * S + s],
                               g_WI[(b * NH + h) * S + s]);
    }
    __syncthreads();
    float ar[NH], ai[NH];
    #pragma unroll
    for (int h = 0; h < NH; h++) { ar[h] = 0.f; ai[h] = 0.f; }
    size_t rbase = ((size_t)b * E + e) * HW;
    const float4* rowr = (const float4*)(g_XPR + rbase);
    const float4* rowi = (const float4*)(g_XPI + rbase);
    #pragma unroll
    for (int it = 0; it < 2; it++) {
        int idx = it * 32 + lane;
        float4 xr4 = rowr[idx];
        float4 xi4 = rowi[idx];
        int sb = idx * 4 + 1;
        #pragma unroll
        for (int h = 0; h < NH; h++) {
            cfma(ar[h], ai[h], ws[h][sb + 0].x, ws[h][sb + 0].y, xr4.x, xi4.x);
            cfma(ar[h], ai[h], ws[h][sb + 1].x, ws[h][sb + 1].y, xr4.y, xi4.y);
            cfma(ar[h], ai[h], ws[h][sb + 2].x, ws[h][sb + 2].y, xr4.z, xi4.z);
            cfma(ar[h], ai[h], ws[h][sb + 3].x, ws[h][sb + 3].y, xr4.w, xi4.w);
        }
    }
    #pragma unroll
    for (int h = 0; h < NH; h++) {
        #pragma unroll
        for (int o = 16; o; o >>= 1) {
            ar[h] += __shfl_xor_sync(0xffffffffu, ar[h], o);
            ai[h] += __shfl_xor_sync(0xffffffffu, ai[h], o);
        }
    }
    if (lane == 0) {
        float x0r = g_X0R[b * E + e], x0i = g_X0I[b * E + e];
        #pragma unroll
        for (int h = 0; h < NH; h++) {
            float rr = ar[h], ii = ai[h];
            cfma(rr, ii, ws[h][0].x, ws[h][0].y, x0r, x0i);   // + w_0 * x0 (mean token)
            g_XWR[(b * NH + h) * E + e] = rr;
            g_XWI[(b * NH + h) * E + e] = ii;
        }
    }
}

// ---------------- 6. attn[b, h*HD+d] = sum_e xw[b,h,e]*w_v[h*HD+d, e] + (1+i)b_v ---
// grid (B, NH, 2); block handles 32 of the 64 d's
__global__ void k_attn(const float* __restrict__ wr, const float* __restrict__ wi,
                       const float* __restrict__ br, const float* __restrict__ bi) {
    int b = blockIdx.x, h = blockIdx.y, z = blockIdx.z;
    int t = threadIdx.x, warp = t >> 5, lane = t & 31;     // 256 thr = 8 warps
    __shared__ float2 xs[E];
    for (int e = t; e < E; e += 256)
        xs[e] = make_float2(g_XWR[(b * NH + h) * E + e], g_XWI[(b * NH + h) * E + e]);
    __syncthreads();
    #pragma unroll
    for (int k = 0; k < 4; k++) {
        int d = z * 32 + warp + 8 * k;
        int row = 2 * E + h * HD + d;                      // v block: rows [2E, 3E)
        float ar, ai;
        cdot_row(wr + (size_t)row * E, wi + (size_t)row * E, xs, lane, ar, ai);
        if (lane == 0) {
            float bvr = br[row], bvi = bi[row];
            g_ATR[b * E + h * HD + d] = ar + (bvr - bvi);  // + (1+i)*(bvr + i bvi)
            g_ATI[b * E + h * HD + d] = ai + (bvr + bvi);
        }
    }
}

// ---------------- complex GEMV: out[b,f] = sum_e in[b,e]*w[f,e] + bias[f] ----------
__device__ __forceinline__ void cproj_body(const float* inr, const float* ini,
                                           const float* __restrict__ wr, const float* __restrict__ wi,
                                           const float* __restrict__ br, const float* __restrict__ bi,
                                           float* outr, float* outi) {
    int b = blockIdx.x, t = threadIdx.x, warp = t >> 5, lane = t & 31;  // 256 thr
    __shared__ float2 xc[E];
    for (int e = t; e < E; e += 256)
        xc[e] = make_float2(inr[b * E + e], ini[b * E + e]);
    __syncthreads();
    int f0 = blockIdx.y * 64;
    #pragma unroll
    for (int k = 0; k < 8; k++) {
        int f = f0 + warp + 8 * k;
        float ar, ai;
        cdot_row(wr + (size_t)f * E, wi + (size_t)f * E, xc, lane, ar, ai);
        if (lane == 0) {
            outr[b * E + f] = ar + br[f];
            outi[b * E + f] = ai + bi[f];
        }
    }
}

// ---------------- 7. out-projection ----------------
__global__ void k_oproj(const float* __restrict__ wr, const float* __restrict__ wi,
                        const float* __restrict__ br, const float* __restrict__ bi) {
    cproj_body(g_ATR, g_ATI, wr, wi, br, bi, g_OR, g_OI);
}

// ---------------- 8. final projection -> PLANAR output: [real plane | imag plane] --
__global__ void k_final(const float* __restrict__ wr, const float* __restrict__ wi,
                        const float* __restrict__ br, const float* __restrict__ bi,
                        float* __restrict__ out) {
    cproj_body(g_OR, g_OI, wr, wi, br, bi, out, out + B * E);
}

extern "C" void kernel_launch(void* const* d_in, const int* in_sizes, int n_in,
                              void* d_out, int out_size) {
    const float* xr   = (const float*)d_in[0];
    const float* xi   = (const float*)d_in[1];
    const float* pr   = (const float*)d_in[2];
    const float* pi   = (const float*)d_in[3];
    const float* winr = (const float*)d_in[4];
    const float* wini = (const float*)d_in[5];
    const float* binr = (const float*)d_in[6];
    const float* bini = (const float*)d_in[7];
    const float* wor  = (const float*)d_in[8];
    const float* woi  = (const float*)d_in[9];
    const float* bor  = (const float*)d_in[10];
    const float* boi  = (const float*)d_in[11];
    const float* wpr  = (const float*)d_in[12];
    const float* wpi  = (const float*)d_in[13];
    const float* bpr  = (const float*)d_in[14];
    const float* bpi  = (const float*)d_in[15];
    float* out = (float*)d_out;

    k_zero   <<<(B * NH * S + 255) / 256, 256>>>();
    k_prep   <<<dim3(B, 64), 256>>>(xr, xi, pr, pi);
    k_q      <<<dim3(B, 8), 256>>>(winr, wini, binr, bini);
    k_qk     <<<dim3(B, NH), 512>>>(winr, wini);
    k_logits <<<dim3(B, NCH), 128>>>();
    k_softmax<<<dim3(B, NH), 288>>>();
    k_xw     <<<dim3(B, 32), 512>>>();
    k_attn   <<<dim3(B, NH, 2), 256>>>(winr, wini, binr, bini);
    k_oproj  <<<dim3(B, 8), 256>>>(wor, woi, bor, boi);
    k_final  <<<dim3(B, 8), 256>>>(wpr, wpi, bpr, bpi, out);
}

// round 17
// speedup vs baseline: 1.4227x; 1.4227x over previous
#include <cuda_runtime.h>

#define B    32
#define E    512
#define HW   256
#define NH   8
#define HD   64
#define S    257
#define NCH  32    // e-chunks for logits
#define ECH  16    // 16 e per chunk

// ---------------- scratch (device globals; no allocation allowed) ----------------
__device__ float g_X0R[B * E],        g_X0I[B * E];         // mean token + pos, s=0
__device__ float g_QR [B * E],        g_QI [B * E];         // q projection at s=0
__device__ float g_QKR[B * NH * E],   g_QKI[B * NH * E];    // q folded into w_k (incl 1/8)
__device__ float g_LR [B * NH * S],   g_LI [B * NH * S];    // logits (atomic accum)
__device__ float g_L0R[B * NH],       g_L0I[B * NH];        // s=0 logit
__device__ float g_WR[B * NH * S],    g_WI[B * NH * S];     // softmax weights
__device__ float g_XWR[B * NH * E],   g_XWI[B * NH * E];    // sum_s w_s * x[s,e]
__device__ float g_ATR[B * E],        g_ATI[B * E];         // attention output row
__device__ float g_OR[B * E],         g_OI[B * E];          // after out-projection

// complex fused-multiply-add: (ar,ai) += (xr + i xi) * (yr + i yi)
__device__ __forceinline__ void cfma(float& ar, float& ai,
                                     float xr, float xi, float yr, float yi) {
    ar = fmaf(xr, yr, ar); ar = fmaf(-xi, yi, ar);
    ai = fmaf(xr, yi, ai); ai = fmaf(xi, yr, ai);
}

// warp-collective complex dot of one weight row (length E, float4 loads) with smem x
__device__ __forceinline__ void cdot_row(const float* __restrict__ wrow_r,
                                         const float* __restrict__ wrow_i,
                                         const float2* __restrict__ xc,
                                         int lane, float& ar, float& ai) {
    const float4* wr4 = (const float4*)wrow_r;
    const float4* wi4 = (const float4*)wrow_i;
    ar = 0.f; ai = 0.f;
    #pragma unroll
    for (int j = 0; j < E / 128; j++) {             // 4 iterations
        float4 a = wr4[j * 32 + lane];
        float4 c = wi4[j * 32 + lane];
        int e = (j * 32 + lane) * 4;
        float2 x0 = xc[e], x1 = xc[e + 1], x2 = xc[e + 2], x3 = xc[e + 3];
        cfma(ar, ai, x0.x, x0.y, a.x, c.x);
        cfma(ar, ai, x1.x, x1.y, a.y, c.y);
        cfma(ar, ai, x2.x, x2.y, a.z, c.z);
        cfma(ar, ai, x3.x, x3.y, a.w, c.w);
    }
    #pragma unroll
    for (int o = 16; o; o >>= 1) {
        ar += __shfl_xor_sync(0xffffffffu, ar, o);
        ai += __shfl_xor_sync(0xffffffffu, ai, o);
    }
}

// ---------------- 0. zero the logits accumulators ----------------
__global__ void k_zero() {
    int i = blockIdx.x * 256 + threadIdx.x;
    if (i < B * NH * S) { g_LR[i] = 0.f; g_LI[i] = 0.f; }
}

// ---------------- 1. x0[b,e] = mean_hw x[b,e,:] + pos[e,0] ----------------
// one warp per (b,e) row; grid (B, 64) x 8 warps
__global__ void k_prep(const float* __restrict__ xr, const float* __restrict__ xi,
                       const float* __restrict__ pr, const float* __restrict__ pi) {
    int b = blockIdx.x;
    int warp = threadIdx.x >> 5, lane = threadIdx.x & 31;
    int e = blockIdx.y * 8 + warp;
    const float4* rowr = (const float4*)(xr + ((size_t)b * E + e) * HW);
    const float4* rowi = (const float4*)(xi + ((size_t)b * E + e) * HW);
    float4 a0 = rowr[lane], a1 = rowr[lane + 32];
    float4 c0 = rowi[lane], c1 = rowi[lane + 32];
    float sr = (a0.x + a0.y) + (a0.z + a0.w) + (a1.x + a1.y) + (a1.z + a1.w);
    float si = (c0.x + c0.y) + (c0.z + c0.w) + (c1.x + c1.y) + (c1.z + c1.w);
    #pragma unroll
    for (int o = 16; o; o >>= 1) {
        sr += __shfl_xor_sync(0xffffffffu, sr, o);
        si += __shfl_xor_sync(0xffffffffu, si, o);
    }
    if (lane == 0) {
        g_X0R[b * E + e] = sr * (1.f / HW) + pr[e * S + 0];
        g_X0I[b * E + e] = si * (1.f / HW) + pi[e * S + 0];
    }
}

// ---------------- 2a. q[b,f] = sum_e x0[b,e] * w_in[f,e] + b_in[f]  (f in [0,E)) ---
__global__ void k_q(const float* __restrict__ wr, const float* __restrict__ wi,
                    const float* __restrict__ br, const float* __restrict__ bi) {
    int b = blockIdx.x, t = threadIdx.x, warp = t >> 5, lane = t & 31;  // 256 thr
    __shared__ float2 xc[E];
    for (int e = t; e < E; e += 256)
        xc[e] = make_float2(g_X0R[b * E + e], g_X0I[b * E + e]);
    __syncthreads();
    int f0 = blockIdx.y * 64;
    #pragma unroll
    for (int k = 0; k < 8; k++) {
        int f = f0 + warp + 8 * k;
        float ar, ai;
        cdot_row(wr + (size_t)f * E, wi + (size_t)f * E, xc, lane, ar, ai);
        if (lane == 0) {
            g_QR[b * E + f] = ar + br[f];
            g_QI[b * E + f] = ai + bi[f];
        }
    }
}

// ---------------- 2b. qk[b,h,e] = (1/8) sum_d q[b,h,d]*w_k[hd,e]; also s=0 logit ---
// 4 independent accumulator pairs break the serial FMA chain (latency-bound kernel)
__global__ void k_qk(const float* __restrict__ wr, const float* __restrict__ wi) {
    int b = blockIdx.x, h = blockIdx.y, t = threadIdx.x;   // 512 threads, t = e
    int warp = t >> 5, lane = t & 31;
    __shared__ float2 qs[HD];
    __shared__ float sred[16][2];
    if (t < HD)
        qs[t] = make_float2(g_QR[b * E + h * HD + t] * 0.125f,
                            g_QI[b * E + h * HD + t] * 0.125f);
    __syncthreads();
    float ar0 = 0.f, ai0 = 0.f, ar1 = 0.f, ai1 = 0.f;
    float ar2 = 0.f, ai2 = 0.f, ar3 = 0.f, ai3 = 0.f;
    size_t rbase = (size_t)(E + h * HD) * E + t;           // k block: rows [E, 2E)
    #pragma unroll 4
    for (int d = 0; d < HD; d += 4) {
        size_t r0 = rbase + (size_t)d * E;
        float w0r = wr[r0],         w0i = wi[r0];
        float w1r = wr[r0 + E],     w1i = wi[r0 + E];
        float w2r = wr[r0 + 2 * E], w2i = wi[r0 + 2 * E];
        float w3r = wr[r0 + 3 * E], w3i = wi[r0 + 3 * E];
        cfma(ar0, ai0, qs[d + 0].x, qs[d + 0].y, w0r, w0i);
        cfma(ar1, ai1, qs[d + 1].x, qs[d + 1].y, w1r, w1i);
        cfma(ar2, ai2, qs[d + 2].x, qs[d + 2].y, w2r, w2i);
        cfma(ar3, ai3, qs[d + 3].x, qs[d + 3].y, w3r, w3i);
    }
    float ar = (ar0 + ar1) + (ar2 + ar3);
    float ai = (ai0 + ai1) + (ai2 + ai3);
    g_QKR[(b * NH + h) * E + t] = ar;
    g_QKI[(b * NH + h) * E + t] = ai;
    // s=0 logit: sum_e x0[b,e] * qk[b,h,e]
    float x0r = g_X0R[b * E + t], x0i = g_X0I[b * E + t];
    float p_r = 0.f, p_i = 0.f;
    cfma(p_r, p_i, x0r, x0i, ar, ai);
    #pragma unroll
    for (int o = 16; o; o >>= 1) {
        p_r += __shfl_xor_sync(0xffffffffu, p_r, o);
        p_i += __shfl_xor_sync(0xffffffffu, p_i, o);
    }
    if (lane == 0) { sred[warp][0] = p_r; sred[warp][1] = p_i; }
    __syncthreads();
    if (t == 0) {
        float a = 0.f, c = 0.f;
        #pragma unroll
        for (int w = 0; w < 16; w++) { a += sred[w][0]; c += sred[w][1]; }
        g_L0R[b * NH + h] = a;
        g_L0I[b * NH + h] = c;
    }
}

// ---------------- 3. logits (s>=1): atomic-accumulate over e chunks ----------------
// grid (B, NCH), 128 threads; thread t handles s = 2t+1, 2t+2 via float2 x loads
__global__ void k_logits(const float* __restrict__ xr, const float* __restrict__ xi,
                         const float* __restrict__ pr, const float* __restrict__ pi) {
    int b = blockIdx.x, c = blockIdx.y, t = threadIdx.x;   // 128 threads
    __shared__ float2 qk[NH][ECH];
    int e0 = c * ECH;
    {
        int h = t / ECH, e = t % ECH;                      // 128 = NH*ECH exactly
        qk[h][e] = make_float2(g_QKR[(b * NH + h) * E + e0 + e],
                               g_QKI[(b * NH + h) * E + e0 + e]);
    }
    __syncthreads();
    int hw0 = 2 * t;
    float lr0[NH], li0[NH], lr1[NH], li1[NH];
    #pragma unroll
    for (int h = 0; h < NH; h++) { lr0[h] = li0[h] = lr1[h] = li1[h] = 0.f; }
    #pragma unroll 4
    for (int ee = 0; ee < ECH; ee++) {
        int e = e0 + ee;
        size_t base = ((size_t)b * E + e) * HW + hw0;
        float2 xrv = *(const float2*)&xr[base];
        float2 xiv = *(const float2*)&xi[base];
        float pr0 = pr[(size_t)e * S + hw0 + 1], pr1 = pr[(size_t)e * S + hw0 + 2];
        float pi0 = pi[(size_t)e * S + hw0 + 1], pi1 = pi[(size_t)e * S + hw0 + 2];
        float x0r = xrv.x + pr0, x0i = xiv.x + pi0;
        float x1r = xrv.y + pr1, x1i = xiv.y + pi1;
        #pragma unroll
        for (int h = 0; h < NH; h++) {
            float2 q = qk[h][ee];
            cfma(lr0[h], li0[h], x0r, x0i, q.x, q.y);
            cfma(lr1[h], li1[h], x1r, x1i, q.x, q.y);
        }
    }
    int s = hw0 + 1;
    #pragma unroll
    for (int h = 0; h < NH; h++) {
        int base = (b * NH + h) * S + s;
        atomicAdd(&g_LR[base],     lr0[h]);
        atomicAdd(&g_LR[base + 1], lr1[h]);
        atomicAdd(&g_LI[base],     li0[h]);
        atomicAdd(&g_LI[base + 1], li1[h]);
    }
}

// ---------------- 4. softmax over s, separately on real and imag parts ----------
__global__ void k_softmax() {
    int b = blockIdx.x, h = blockIdx.y, t = threadIdx.x;   // 288 threads = 9 warps
    __shared__ float swr[9], swi[9], smax[2], ssum[2];
    bool act = t < S;
    float vr = 0.f, vi = 0.f;
    if (act) {
        if (t == 0) { vr = g_L0R[b * NH + h]; vi = g_L0I[b * NH + h]; }
        else        { vr = g_LR[(b * NH + h) * S + t]; vi = g_LI[(b * NH + h) * S + t]; }
    }
    int warp = t >> 5, lane = t & 31;
    float mr = act ? vr : -1e30f, mi = act ? vi : -1e30f;
    #pragma unroll
    for (int o = 16; o; o >>= 1) {
        mr = fmaxf(mr, __shfl_xor_sync(0xffffffffu, mr, o));
        mi = fmaxf(mi, __shfl_xor_sync(0xffffffffu, mi, o));
    }
    if (lane == 0) { swr[warp] = mr; swi[warp] = mi; }
    __syncthreads();
    if (t == 0) {
        float a = -1e30f, c2 = -1e30f;
        for (int w = 0; w < 9; w++) { a = fmaxf(a, swr[w]); c2 = fmaxf(c2, swi[w]); }
        smax[0] = a; smax[1] = c2;
    }
    __syncthreads();
    float er = act ? expf(vr - smax[0]) : 0.f;
    float ei = act ? expf(vi - smax[1]) : 0.f;
    float sr = er, si = ei;
    #pragma unroll
    for (int o = 16; o; o >>= 1) {
        sr += __shfl_xor_sync(0xffffffffu, sr, o);
        si += __shfl_xor_sync(0xffffffffu, si, o);
    }
    __syncthreads();
    if (lane == 0) { swr[warp] = sr; swi[warp] = si; }
    __syncthreads();
    if (t == 0) {
        float a = 0.f, c2 = 0.f;
        for (int w = 0; w < 9; w++) { a += swr[w]; c2 += swi[w]; }
        ssum[0] = a; ssum[1] = c2;
    }
    __syncthreads();
    if (act) {
        g_WR[(b * NH + h) * S + t] = er / ssum[0];
        g_WI[(b * NH + h) * S + t] = ei / ssum[1];
    }
}

// ---------------- 5. xw[b,h,e] = sum_s w[b,h,s] * x[b,s,e] (complex) --------------
__global__ void k_xw(const float* __restrict__ xr, const float* __restrict__ xi,
                     const float* __restrict__ pr, const float* __restrict__ pi) {
    int b = blockIdx.x;
    int t = threadIdx.x, warp = t >> 5, lane = t & 31;     // 512 thr = 16 warps
    int e = blockIdx.y * 16 + warp;
    __shared__ float2 ws[NH][S];                           // 16448 B
    for (int idx = t; idx < NH * S; idx += 512) {
        int h = idx / S, s = idx % S;
        ws[h][s] = make_float2(g_WR[(b * NH + h) * S + s],
                               g_WI[(b * NH + h) * S + s]);
    }
    __syncthreads();
    float ar[NH], ai[NH];
    #pragma unroll
    for (int h = 0; h < NH; h++) { ar[h] = 0.f; ai[h] = 0.f; }
    const float* rowr = xr + ((size_t)b * E + e) * HW;
    const float* rowi = xi + ((size_t)b * E + e) * HW;
    #pragma unroll
    for (int it = 0; it < HW / 32; it++) {
        int hw = it * 32 + lane;
        int s = hw + 1;
        float xrv = rowr[hw] + pr[e * S + s];
        float xiv = rowi[hw] + pi[e * S + s];
        #pragma unroll
        for (int h = 0; h < NH; h++)
            cfma(ar[h], ai[h], ws[h][s].x, ws[h][s].y, xrv, xiv);
    }
    #pragma unroll
    for (int h = 0; h < NH; h++) {
        #pragma unroll
        for (int o = 16; o; o >>= 1) {
            ar[h] += __shfl_xor_sync(0xffffffffu, ar[h], o);
            ai[h] += __shfl_xor_sync(0xffffffffu, ai[h], o);
        }
    }
    if (lane == 0) {
        float x0r = g_X0R[b * E + e], x0i = g_X0I[b * E + e];
        #pragma unroll
        for (int h = 0; h < NH; h++) {
            float rr = ar[h], ii = ai[h];
            cfma(rr, ii, ws[h][0].x, ws[h][0].y, x0r, x0i);   // + w_0 * x0 (mean token)
            g_XWR[(b * NH + h) * E + e] = rr;
            g_XWI[(b * NH + h) * E + e] = ii;
        }
    }
}

// ---------------- 6. attn[b, h*HD+d] = sum_e xw[b,h,e]*w_v[h*HD+d, e] + (1+i)b_v ---
// grid (B, NH, 2); block handles 32 of the 64 d's
__global__ void k_attn(const float* __restrict__ wr, const float* __restrict__ wi,
                       const float* __restrict__ br, const float* __restrict__ bi) {
    int b = blockIdx.x, h = blockIdx.y, z = blockIdx.z;
    int t = threadIdx.x, warp = t >> 5, lane = t & 31;     // 256 thr = 8 warps
    __shared__ float2 xs[E];
    for (int e = t; e < E; e += 256)
        xs[e] = make_float2(g_XWR[(b * NH + h) * E + e], g_XWI[(b * NH + h) * E + e]);
    __syncthreads();
    #pragma unroll
    for (int k = 0; k < 4; k++) {
        int d = z * 32 + warp + 8 * k;
        int row = 2 * E + h * HD + d;                      // v block: rows [2E, 3E)
        float ar, ai;
        cdot_row(wr + (size_t)row * E, wi + (size_t)row * E, xs, lane, ar, ai);
        if (lane == 0) {
            float bvr = br[row], bvi = bi[row];
            g_ATR[b * E + h * HD + d] = ar + (bvr - bvi);  // + (1+i)*(bvr + i bvi)
            g_ATI[b * E + h * HD + d] = ai + (bvr + bvi);
        }
    }
}

// ---------------- complex GEMV: out[b,f] = sum_e in[b,e]*w[f,e] + bias[f] ----------
// grid (B, 8); block handles 64 f's
__device__ __forceinline__ void cproj_body(const float* inr, const float* ini,
                                           const float* __restrict__ wr, const float* __restrict__ wi,
                                           const float* __restrict__ br, const float* __restrict__ bi,
                                           float* outr, float* outi) {
    int b = blockIdx.x, t = threadIdx.x, warp = t >> 5, lane = t & 31;  // 256 thr
    __shared__ float2 xc[E];
    for (int e = t; e < E; e += 256)
        xc[e] = make_float2(inr[b * E + e], ini[b * E + e]);
    __syncthreads();
    int f0 = blockIdx.y * 64;
    #pragma unroll
    for (int k = 0; k < 8; k++) {
        int f = f0 + warp + 8 * k;
        float ar, ai;
        cdot_row(wr + (size_t)f * E, wi + (size_t)f * E, xc, lane, ar, ai);
        if (lane == 0) {
            outr[b * E + f] = ar + br[f];
            outi[b * E + f] = ai + bi[f];
        }
    }
}

// ---------------- 7. out-projection ----------------
__global__ void k_oproj(const float* __restrict__ wr, const float* __restrict__ wi,
                        const float* __restrict__ br, const float* __restrict__ bi) {
    cproj_body(g_ATR, g_ATI, wr, wi, br, bi, g_OR, g_OI);
}

// ---------------- 8. final projection -> PLANAR output: [real plane | imag plane] --
__global__ void k_final(const float* __restrict__ wr, const float* __restrict__ wi,
                        const float* __restrict__ br, const float* __restrict__ bi,
                        float* __restrict__ out) {
    cproj_body(g_OR, g_OI, wr, wi, br, bi, out, out + B * E);
}

extern "C" void kernel_launch(void* const* d_in, const int* in_sizes, int n_in,
                              void* d_out, int out_size) {
    const float* xr   = (const float*)d_in[0];
    const float* xi   = (const float*)d_in[1];
    const float* pr   = (const float*)d_in[2];
    const float* pi   = (const float*)d_in[3];
    const float* winr = (const float*)d_in[4];
    const float* wini = (const float*)d_in[5];
    const float* binr = (const float*)d_in[6];
    const float* bini = (const float*)d_in[7];
    const float* wor  = (const float*)d_in[8];
    const float* woi  = (const float*)d_in[9];
    const float* bor  = (const float*)d_in[10];
    const float* boi  = (const float*)d_in[11];
    const float* wpr  = (const float*)d_in[12];
    const float* wpi  = (const float*)d_in[13];
    const float* bpr  = (const float*)d_in[14];
    const float* bpi  = (const float*)d_in[15];
    float* out = (float*)d_out;

    k_zero   <<<(B * NH * S + 255) / 256, 256>>>();
    k_prep   <<<dim3(B, 64), 256>>>(xr, xi, pr, pi);
    k_q      <<<dim3(B, 8), 256>>>(winr, wini, binr, bini);
    k_qk     <<<dim3(B, NH), 512>>>(winr, wini);
    k_logits <<<dim3(B, NCH), 128>>>(xr, xi, pr, pi);
    k_softmax<<<dim3(B, NH), 288>>>();
    k_xw     <<<dim3(B, 32), 512>>>(xr, xi, pr, pi);
    k_attn   <<<dim3(B, NH, 2), 256>>>(winr, wini, binr, bini);
    k_oproj  <<<dim3(B, 8), 256>>>(wor, woi, bor, boi);
    k_final  <<<dim3(B, 8), 256>>>(wpr, wpi, bpr, bpi, out);
}